// round 3
// baseline (speedup 1.0000x reference)
#include <cuda_runtime.h>
#include <cstdint>
#include <cstddef>

// ---------------- problem constants ----------------
#define Bb   4
#define Np   16384
#define Cf   128
#define Mq   1024
#define Kq   32
#define NNc  131072            // Bb*Mq*Kq
#define R2c  0.16f             // 0.4^2
#define EPSv 1e-5f

// ---------------- scratch (device globals: no allocation allowed) ----------------
__device__ int   g_idx[Bb * Mq * Kq];                 // ball query result
__device__ float g_Y1[(size_t)128 * NNc];             // 64 MB
__device__ float g_Y2[(size_t)128 * NNc];             // 64 MB
__device__ float g_Y3[(size_t)256 * NNc];             // 128 MB
__device__ float g_scale[256];
__device__ float g_shift[256];

// ---------------- kernel 0: gather new_xyz into d_out[0 : B*M*3) ----------------
__global__ void k_newxyz(const float* __restrict__ pxyz, const int* __restrict__ ind,
                         float* __restrict__ out)
{
    int i = blockIdx.x * blockDim.x + threadIdx.x;
    if (i >= Bb * Mq) return;
    int b = i >> 10;                    // M = 1024
    int n = ind[i];
    const float* p = pxyz + ((size_t)b * Np + n) * 3;
    out[i * 3 + 0] = p[0];
    out[i * 3 + 1] = p[1];
    out[i * 3 + 2] = p[2];
}

// ---------------- kernel 1: ball query (one warp per query) ----------------
// Replicates: first K points (index order) with d2 < r2, padded with first found.
__global__ void k_ballquery(const float* __restrict__ pxyz, const float* __restrict__ nxyz)
{
    int gtid = blockIdx.x * blockDim.x + threadIdx.x;
    int q    = gtid >> 5;               // query id, 0..4095
    int lane = gtid & 31;
    int b    = q >> 10;

    float nx = nxyz[q * 3 + 0];
    float ny = nxyz[q * 3 + 1];
    float nz = nxyz[q * 3 + 2];
    const float* px = pxyz + (size_t)b * Np * 3;

    int cnt = 0, first = 0;
    for (int n0 = 0; n0 < Np; n0 += 32) {
        int n = n0 + lane;
        float x = px[n * 3 + 0], y = px[n * 3 + 1], z = px[n * 3 + 2];
        float dx = x - nx, dy = y - ny, dz = z - nz;
        // avoid FMA contraction to match the reference's mul+add rounding
        float d2 = __fadd_rn(__fadd_rn(__fmul_rn(dx, dx), __fmul_rn(dy, dy)),
                             __fmul_rn(dz, dz));
        bool within = d2 < R2c;
        unsigned bal = __ballot_sync(0xffffffffu, within);
        if (bal) {
            if (cnt == 0) first = n0 + __ffs(bal) - 1;
            int pre = __popc(bal & ((1u << lane) - 1u));
            if (within && (cnt + pre) < Kq)
                g_idx[q * Kq + cnt + pre] = n;
            cnt += __popc(bal);
            if (cnt >= Kq) break;       // uniform across warp
        }
    }
    cnt = min(cnt, Kq);
    if (lane >= cnt)                    // pad slots [cnt, 32) with first index
        g_idx[q * Kq + lane] = first;
}

// ---------------- GEMM: Y[o][j] = sum_c W[o][c] * Bmat(c, j) + bias[o] ----------------
// MODE 0: Bmat(c,j) generated on the fly = concat(grouped_xyz, grouped_feat)
// MODE 1: Bmat(c,j) = relu(scale[c]*Yprev[c][j] + shift[c])   (fused BN+ReLU)
// Tile: 128(out-ch) x 128(cols), BK=8, 256 threads, 8x8 per thread via fma.rn.f32x2.
template <int MODE>
__global__ void __launch_bounds__(256, 2) k_gemm(
    const float* __restrict__ W, const float* __restrict__ bias, int KC,
    const float* __restrict__ Bsrc,
    const float* __restrict__ scale, const float* __restrict__ shift,
    float* __restrict__ Y,
    const float* __restrict__ pxyz, const float* __restrict__ feat,
    const float* __restrict__ nxyz)
{
    __shared__ float As[8][128];
    __shared__ float Bs[8][132];        // +4 pad

    const int tid = threadIdx.x;
    const int tr  = tid >> 4;           // 0..15 (rows of 8)
    const int tc  = tid & 15;           // 0..15 (cols of 8)
    const int n0  = blockIdx.x << 7;
    const int o0  = blockIdx.y << 7;

    unsigned long long acc[8][4];       // packed f32x2 accumulators (8x8 floats)
#pragma unroll
    for (int i = 0; i < 8; i++)
#pragma unroll
        for (int j = 0; j < 4; j++) acc[i][j] = 0ull;

    for (int k0 = 0; k0 < KC; k0 += 8) {
        // ---- load A tile: As[k][mo] = W[o0+mo][k0+k] ----
#pragma unroll
        for (int s = 0; s < 4; s++) {
            int i  = tid + (s << 8);    // 0..1023
            int k  = i & 7;
            int mo = i >> 3;
            int c  = k0 + k;
            As[k][mo] = (c < KC) ? W[(size_t)(o0 + mo) * KC + c] : 0.f;
        }
        // ---- load B tile ----
#pragma unroll
        for (int s = 0; s < 4; s++) {
            int i   = tid + (s << 8);
            int k   = i >> 7;
            int j   = i & 127;
            int c   = k0 + k;
            int col = n0 + j;
            float v = 0.f;
            if (c < KC) {
                if (MODE == 0) {
                    int idxv = g_idx[col];
                    int bq   = col >> 15;               // 32768 cols per batch
                    if (c < 3) {
                        int q = col >> 5;
                        v = pxyz[((size_t)bq * Np + idxv) * 3 + c] - nxyz[q * 3 + c];
                    } else {
                        v = feat[((size_t)bq * Cf + (c - 3)) * (size_t)Np + idxv];
                    }
                } else {
                    float y = Bsrc[(size_t)c * NNc + col];
                    v = fmaxf(fmaf(scale[c], y, shift[c]), 0.f);
                }
            }
            Bs[k][j] = v;
        }
        __syncthreads();

        // ---- compute: 8 k-steps, 8x8 outputs per thread, packed f32x2 FMA ----
#pragma unroll
        for (int k = 0; k < 8; k++) {
            float4 b0 = *(const float4*)&Bs[k][tc << 3];
            float4 b1 = *(const float4*)&Bs[k][(tc << 3) + 4];
            unsigned long long bp0, bp1, bp2, bp3;
            asm("mov.b64 %0,{%1,%2};" : "=l"(bp0) : "f"(b0.x), "f"(b0.y));
            asm("mov.b64 %0,{%1,%2};" : "=l"(bp1) : "f"(b0.z), "f"(b0.w));
            asm("mov.b64 %0,{%1,%2};" : "=l"(bp2) : "f"(b1.x), "f"(b1.y));
            asm("mov.b64 %0,{%1,%2};" : "=l"(bp3) : "f"(b1.z), "f"(b1.w));

            float4 a0 = *(const float4*)&As[k][tr << 3];
            float4 a1 = *(const float4*)&As[k][(tr << 3) + 4];
            float av[8] = {a0.x, a0.y, a0.z, a0.w, a1.x, a1.y, a1.z, a1.w};
#pragma unroll
            for (int i = 0; i < 8; i++) {
                unsigned long long ap;
                asm("mov.b64 %0,{%1,%1};" : "=l"(ap) : "f"(av[i]));
                asm("fma.rn.f32x2 %0,%1,%2,%0;" : "+l"(acc[i][0]) : "l"(ap), "l"(bp0));
                asm("fma.rn.f32x2 %0,%1,%2,%0;" : "+l"(acc[i][1]) : "l"(ap), "l"(bp1));
                asm("fma.rn.f32x2 %0,%1,%2,%0;" : "+l"(acc[i][2]) : "l"(ap), "l"(bp2));
                asm("fma.rn.f32x2 %0,%1,%2,%0;" : "+l"(acc[i][3]) : "l"(ap), "l"(bp3));
            }
        }
        __syncthreads();
    }

    // ---- epilogue: add bias, store Y ----
#pragma unroll
    for (int i = 0; i < 8; i++) {
        int o = o0 + (tr << 3) + i;
        float bb = bias[o];
        float v[8];
#pragma unroll
        for (int j2 = 0; j2 < 4; j2++) {
            float lo, hi;
            asm("mov.b64 {%0,%1},%2;" : "=f"(lo), "=f"(hi) : "l"(acc[i][j2]));
            v[j2 * 2]     = lo + bb;
            v[j2 * 2 + 1] = hi + bb;
        }
        float4* dst = (float4*)&Y[(size_t)o * NNc + n0 + (tc << 3)];
        dst[0] = make_float4(v[0], v[1], v[2], v[3]);
        dst[1] = make_float4(v[4], v[5], v[6], v[7]);
    }
}

// ---------------- per-channel BN stats -> scale/shift (deterministic) ----------------
__global__ void k_stats(const float* __restrict__ Y, const float* __restrict__ gam,
                        const float* __restrict__ bet,
                        float* __restrict__ scale, float* __restrict__ shift)
{
    __shared__ float ss[256], sq[256];
    int c = blockIdx.x;
    const float4* row = (const float4*)(Y + (size_t)c * NNc);
    float s = 0.f, q = 0.f;
    for (int i = threadIdx.x; i < NNc / 4; i += 256) {
        float4 v = row[i];
        s += v.x + v.y + v.z + v.w;
        q += v.x * v.x + v.y * v.y + v.z * v.z + v.w * v.w;
    }
    ss[threadIdx.x] = s; sq[threadIdx.x] = q;
    __syncthreads();
    for (int st = 128; st > 0; st >>= 1) {
        if (threadIdx.x < st) {
            ss[threadIdx.x] += ss[threadIdx.x + st];
            sq[threadIdx.x] += sq[threadIdx.x + st];
        }
        __syncthreads();
    }
    if (threadIdx.x == 0) {
        float mean = ss[0] * (1.f / NNc);
        float var  = sq[0] * (1.f / NNc) - mean * mean;
        float rs   = rsqrtf(var + EPSv);
        float sc   = gam[c] * rs;
        scale[c] = sc;
        shift[c] = fmaf(-mean, sc, bet[c]);
    }
}

// ---------------- final: BN3 + ReLU + max over K -> d_out features ----------------
__global__ void k_final(const float* __restrict__ Y3, const float* __restrict__ scale,
                        const float* __restrict__ shift, float* __restrict__ outf)
{
    int i = blockIdx.x * blockDim.x + threadIdx.x;   // over B*256*M = 1048576
    int m = i & (Mq - 1);
    int o = (i >> 10) & 255;
    int b = i >> 18;
    size_t base = (size_t)o * NNc + (((size_t)b << 10) + m) * Kq;
    const float4* p = (const float4*)(Y3 + base);
    float sc = scale[o], sh = shift[o];
    float mx = 0.f;                                  // relu outputs are >= 0
#pragma unroll
    for (int t = 0; t < 8; t++) {
        float4 v = p[t];
        mx = fmaxf(mx, fmaxf(fmaf(sc, v.x, sh), 0.f));
        mx = fmaxf(mx, fmaxf(fmaf(sc, v.y, sh), 0.f));
        mx = fmaxf(mx, fmaxf(fmaf(sc, v.z, sh), 0.f));
        mx = fmaxf(mx, fmaxf(fmaf(sc, v.w, sh), 0.f));
    }
    outf[((size_t)b * 256 + o) * Mq + m] = mx;
}

// ---------------- host launcher ----------------
extern "C" void kernel_launch(void* const* d_in, const int* in_sizes, int n_in,
                              void* d_out, int out_size)
{
    const float* pxyz = (const float*)d_in[0];
    const float* feat = (const float*)d_in[1];
    const int*   ind  = (const int*)d_in[2];
    const float* w1 = (const float*)d_in[3];  const float* b1 = (const float*)d_in[4];
    const float* g1 = (const float*)d_in[5];  const float* be1 = (const float*)d_in[6];
    const float* w2 = (const float*)d_in[7];  const float* b2 = (const float*)d_in[8];
    const float* g2 = (const float*)d_in[9];  const float* be2 = (const float*)d_in[10];
    const float* w3 = (const float*)d_in[11]; const float* b3 = (const float*)d_in[12];
    const float* g3 = (const float*)d_in[13]; const float* be3 = (const float*)d_in[14];

    float* out  = (float*)d_out;
    float* nxyz = out;                       // (B,M,3) region
    float* fout = out + Bb * Mq * 3;         // (B,256,M) region

    float *pY1, *pY2, *pY3, *pScale, *pShift;
    cudaGetSymbolAddress((void**)&pY1, g_Y1);
    cudaGetSymbolAddress((void**)&pY2, g_Y2);
    cudaGetSymbolAddress((void**)&pY3, g_Y3);
    cudaGetSymbolAddress((void**)&pScale, g_scale);
    cudaGetSymbolAddress((void**)&pShift, g_shift);

    k_newxyz<<<(Bb * Mq + 255) / 256, 256>>>(pxyz, ind, nxyz);
    k_ballquery<<<(Bb * Mq * 32) / 256, 256>>>(pxyz, nxyz);

    // layer 1: fused gather/concat GEMM (KC=131)
    k_gemm<0><<<dim3(NNc / 128, 1), 256>>>(w1, b1, 131, nullptr, nullptr, nullptr,
                                           pY1, pxyz, feat, nxyz);
    k_stats<<<128, 256>>>(pY1, g1, be1, pScale, pShift);

    // layer 2 (BN1+ReLU fused into B-load)
    k_gemm<1><<<dim3(NNc / 128, 1), 256>>>(w2, b2, 128, pY1, pScale, pShift,
                                           pY2, nullptr, nullptr, nullptr);
    k_stats<<<128, 256>>>(pY2, g2, be2, pScale, pShift);

    // layer 3 (BN2+ReLU fused), 256 output channels
    k_gemm<1><<<dim3(NNc / 128, 2), 256>>>(w3, b3, 128, pY2, pScale, pShift,
                                           pY3, nullptr, nullptr, nullptr);
    k_stats<<<256, 256>>>(pY3, g3, be3, pScale, pShift);

    // BN3 + ReLU + max over K
    k_final<<<(Bb * 256 * Mq) / 256, 256>>>(pY3, pScale, pShift, fout);
}